// round 1
// baseline (speedup 1.0000x reference)
#include <cuda_runtime.h>

// Problem constants
#define N_    32
#define C_    256
#define H_    56
#define W_    56
#define OC_   256

// Tiling
#define CK    8      // cin per smem chunk
#define OCT   128    // oc per block
#define TPX   7      // px per thread
#define TOC   8      // oc per thread
#define NTHR  128    // threads per block (16 oc-groups x 8 w-groups)

// Dequantized, transposed weights: [cin][kh][kw][oc]  (2.36 MB, static device scratch)
__device__ __align__(16) float g_wt[C_ * 9 * OC_];

// ---------------------------------------------------------------------------
// Kernel A: dequantize + transpose weights.
// q layout: [oc][cin][3][3]; write wt[(cin*9 + k)*256 + oc] = q*scale + wmin
// ---------------------------------------------------------------------------
__global__ void dequant_kernel(const int* __restrict__ q,
                               const float* __restrict__ scale,
                               const float* __restrict__ wmin) {
    int i = blockIdx.x * blockDim.x + threadIdx.x;
    if (i >= OC_ * C_ * 9) return;
    float s = *scale;
    float m = *wmin;
    int oc  = i / (C_ * 9);
    int rem = i % (C_ * 9);          // cin*9 + (kh*3+kw)
    g_wt[rem * OC_ + oc] = (float)q[i] * s + m;
}

// ---------------------------------------------------------------------------
// Kernel B: direct 3x3 conv, pad=1, stride=1.
// grid = (2 oc-tiles, 56 rows, 32 images), block = 128 threads.
// Each thread: 8 oc x 7 px accumulators.
// ---------------------------------------------------------------------------
__global__ void __launch_bounds__(NTHR, 4)
conv_kernel(const float* __restrict__ x,
            const float* __restrict__ bias,
            float* __restrict__ out) {
    __shared__ __align__(16) float s_w[CK * 9 * OCT];   // [ck][k][ocl]   36864 B
    __shared__ float s_x[CK * 3 * 60];                  // [ck][r][60]     5760 B

    const int oc0 = blockIdx.x * OCT;
    const int oh  = blockIdx.y;
    const int n   = blockIdx.z;
    const int tid = threadIdx.x;
    const int wg  = tid & 7;        // 0..7  : w group (7 px each)
    const int og  = tid >> 3;       // 0..15 : oc group (8 oc each)
    const int ow0  = wg * TPX;
    const int ocl0 = og * TOC;

    float acc[TOC][TPX];
#pragma unroll
    for (int o = 0; o < TOC; o++)
#pragma unroll
        for (int p = 0; p < TPX; p++) acc[o][p] = 0.0f;

    const float* xbase = x + (long)n * C_ * H_ * W_;

    for (int cc = 0; cc < C_; cc += CK) {
        // ---- stage weights: 8*9*128 floats, contiguous in g_wt for this
        //      (cin-chunk, oc-tile), as float4 ----
#pragma unroll
        for (int j4 = tid; j4 < CK * 9 * OCT / 4; j4 += NTHR) {
            int j   = j4 * 4;
            int row = j / OCT;                 // (ck*9 + k)
            int ocl = j % OCT;
            const float* src = g_wt + ((long)(cc * 9 + row)) * OC_ + oc0 + ocl;
            *(float4*)&s_w[j] = *(const float4*)src;
        }
        // ---- stage input: 8 cin x 3 rows x 58 cols (with zero halo) ----
        for (int j = tid; j < CK * 3 * 58; j += NTHR) {
            int ck  = j / (3 * 58);
            int rem = j % (3 * 58);
            int r   = rem / 58;
            int c   = rem % 58;
            int ih  = oh - 1 + r;
            int iw  = c - 1;
            float v = 0.0f;
            if ((unsigned)ih < H_ && (unsigned)iw < W_)
                v = xbase[((cc + ck) * H_ + ih) * W_ + iw];
            s_x[(ck * 3 + r) * 60 + c] = v;
        }
        __syncthreads();

        // ---- compute ----
#pragma unroll 1
        for (int ck = 0; ck < CK; ck++) {
#pragma unroll
            for (int kh = 0; kh < 3; kh++) {
                float xv[TPX + 2];
#pragma unroll
                for (int i = 0; i < TPX + 2; i++)
                    xv[i] = s_x[(ck * 3 + kh) * 60 + ow0 + i];
#pragma unroll
                for (int kw = 0; kw < 3; kw++) {
                    const float* wp = &s_w[((ck * 3 + kh) * 3 + kw) * OCT + ocl0];
                    float4 a = *(const float4*)wp;
                    float4 b = *(const float4*)(wp + 4);
                    float wv[TOC];
                    wv[0] = a.x; wv[1] = a.y; wv[2] = a.z; wv[3] = a.w;
                    wv[4] = b.x; wv[5] = b.y; wv[6] = b.z; wv[7] = b.w;
#pragma unroll
                    for (int o = 0; o < TOC; o++)
#pragma unroll
                        for (int p = 0; p < TPX; p++)
                            acc[o][p] = fmaf(wv[o], xv[p + kw], acc[o][p]);
                }
            }
        }
        __syncthreads();
    }

    // ---- epilogue: add bias, store ----
#pragma unroll
    for (int o = 0; o < TOC; o++) {
        int oc = oc0 + ocl0 + o;
        float b = __ldg(&bias[oc]);
        float* op = out + (((long)n * OC_ + oc) * H_ + oh) * W_ + ow0;
#pragma unroll
        for (int p = 0; p < TPX; p++)
            op[p] = acc[o][p] + b;
    }
}

// ---------------------------------------------------------------------------
// Launch: inputs (metadata order): x, q_weight, w_scale, w_min, bias
// ---------------------------------------------------------------------------
extern "C" void kernel_launch(void* const* d_in, const int* in_sizes, int n_in,
                              void* d_out, int out_size) {
    const float* x    = (const float*)d_in[0];
    const int*   q    = (const int*)  d_in[1];
    const float* ws   = (const float*)d_in[2];
    const float* wm   = (const float*)d_in[3];
    const float* bias = (const float*)d_in[4];
    float* out = (float*)d_out;

    (void)in_sizes; (void)n_in; (void)out_size;

    dequant_kernel<<<(OC_ * C_ * 9 + 255) / 256, 256>>>(q, ws, wm);

    dim3 grid(OC_ / OCT, H_, N_);   // (2, 56, 32)
    conv_kernel<<<grid, NTHR>>>(x, bias, out);
}

// round 3
// speedup vs baseline: 1.0692x; 1.0692x over previous
#include <cuda_runtime.h>

// Problem constants
#define N_    32
#define C_    256
#define H_    56
#define W_    56
#define OC_   256

// Tiling
#define CK    8      // cin per smem chunk
#define OCT   128    // oc per block
#define TPX   7      // px per thread
#define TOC   8      // oc per thread (4 packed pairs)
#define NTHR  128    // threads per block (16 oc-groups x 8 w-groups)

typedef unsigned long long u64;

// Dequantized, transposed weights: [cin][kh][kw][oc]  (2.36 MB, static device scratch)
__device__ __align__(16) float g_wt[C_ * 9 * OC_];

// ---- packed fp32x2 helpers (Blackwell FFMA2, PTX-only) ----
__device__ __forceinline__ u64 fma2(u64 a, u64 b, u64 c) {
    u64 d;
    asm("fma.rn.f32x2 %0, %1, %2, %3;" : "=l"(d) : "l"(a), "l"(b), "l"(c));
    return d;
}
__device__ __forceinline__ u64 bcast2(float v) {
    u64 d;
    asm("mov.b64 %0, {%1, %1};" : "=l"(d) : "f"(v));
    return d;
}
__device__ __forceinline__ u64 pack2(float lo, float hi) {
    u64 d;
    asm("mov.b64 %0, {%1, %2};" : "=l"(d) : "f"(lo), "f"(hi));
    return d;
}
__device__ __forceinline__ float lo2(u64 v) {
    return __uint_as_float((unsigned)(v & 0xffffffffull));
}
__device__ __forceinline__ float hi2(u64 v) {
    return __uint_as_float((unsigned)(v >> 32));
}

// ---------------------------------------------------------------------------
// Kernel A: dequantize + transpose weights.
// q layout: [oc][cin][3][3]; write wt[(cin*9 + k)*256 + oc] = q*scale + wmin
// ---------------------------------------------------------------------------
__global__ void dequant_kernel(const int* __restrict__ q,
                               const float* __restrict__ scale,
                               const float* __restrict__ wmin) {
    int i = blockIdx.x * blockDim.x + threadIdx.x;
    if (i >= OC_ * C_ * 9) return;
    float s = *scale;
    float m = *wmin;
    int oc  = i / (C_ * 9);
    int rem = i % (C_ * 9);          // cin*9 + (kh*3+kw)
    g_wt[rem * OC_ + oc] = (float)q[i] * s + m;
}

// ---------------------------------------------------------------------------
// Kernel B: direct 3x3 conv, pad=1, stride=1, packed f32x2 math.
// grid = (2 oc-tiles, 56 rows, 32 images), block = 128 threads.
// Each thread: 8 oc x 7 px accumulators, stored as 4x7 packed f32x2.
// ---------------------------------------------------------------------------
__global__ void __launch_bounds__(NTHR, 4)
conv_kernel(const float* __restrict__ x,
            const float* __restrict__ bias,
            float* __restrict__ out) {
    __shared__ __align__(16) float s_w[CK * 9 * OCT];   // [ck][k][ocl]   36864 B
    __shared__ float s_x[CK * 3 * 60];                  // [ck][r][60]     5760 B

    const int oc0 = blockIdx.x * OCT;
    const int oh  = blockIdx.y;
    const int n   = blockIdx.z;
    const int tid = threadIdx.x;
    const int wg  = tid & 7;        // 0..7  : w group (7 px each)
    const int og  = tid >> 3;       // 0..15 : oc group (8 oc each)
    const int ow0  = wg * TPX;
    const int ocl0 = og * TOC;

    // acc2[o2][p]: lanes = (oc = ocl0+2*o2, oc = ocl0+2*o2+1)
    u64 acc2[TOC / 2][TPX];
#pragma unroll
    for (int o = 0; o < TOC / 2; o++)
#pragma unroll
        for (int p = 0; p < TPX; p++) acc2[o][p] = 0ULL;

    const float* xbase = x + (long)n * C_ * H_ * W_;

    for (int cc = 0; cc < C_; cc += CK) {
        // ---- stage weights: 8*9*128 floats contiguous in g_wt ----
#pragma unroll
        for (int j4 = tid; j4 < CK * 9 * OCT / 4; j4 += NTHR) {
            int j   = j4 * 4;
            int row = j / OCT;                 // (ck*9 + k)
            int ocl = j % OCT;
            const float* src = g_wt + ((long)(cc * 9 + row)) * OC_ + oc0 + ocl;
            *(float4*)&s_w[j] = *(const float4*)src;
        }
        // ---- stage input: 8 cin x 3 rows x 58 cols (zero halo) ----
        for (int j = tid; j < CK * 3 * 58; j += NTHR) {
            int ck  = j / (3 * 58);
            int rem = j % (3 * 58);
            int r   = rem / 58;
            int c   = rem % 58;
            int ih  = oh - 1 + r;
            int iw  = c - 1;
            float v = 0.0f;
            if ((unsigned)ih < H_ && (unsigned)iw < W_)
                v = xbase[((cc + ck) * H_ + ih) * W_ + iw];
            s_x[(ck * 3 + r) * 60 + c] = v;
        }
        __syncthreads();

        // ---- compute ----
#pragma unroll 1
        for (int ck = 0; ck < CK; ck++) {
#pragma unroll
            for (int kh = 0; kh < 3; kh++) {
                // 9 input pixels, broadcast-packed into f32x2
                u64 xp[TPX + 2];
#pragma unroll
                for (int i = 0; i < TPX + 2; i++)
                    xp[i] = bcast2(s_x[(ck * 3 + kh) * 60 + ow0 + i]);
#pragma unroll
                for (int kw = 0; kw < 3; kw++) {
                    const float* wp = &s_w[((ck * 3 + kh) * 3 + kw) * OCT + ocl0];
                    // 8 contiguous oc weights = 4 packed pairs (two LDS.128)
                    float4 wa = *(const float4*)wp;        // oc 0-3
                    float4 wb = *(const float4*)(wp + 4);  // oc 4-7
                    u64 wv2[4];
                    wv2[0] = pack2(wa.x, wa.y);
                    wv2[1] = pack2(wa.z, wa.w);
                    wv2[2] = pack2(wb.x, wb.y);
                    wv2[3] = pack2(wb.z, wb.w);
#pragma unroll
                    for (int o = 0; o < TOC / 2; o++)
#pragma unroll
                        for (int p = 0; p < TPX; p++)
                            acc2[o][p] = fma2(wv2[o], xp[p + kw], acc2[o][p]);
                }
            }
        }
        __syncthreads();
    }

    // ---- epilogue: add bias, store ----
#pragma unroll
    for (int o = 0; o < TOC / 2; o++) {
        int oc_e = oc0 + ocl0 + 2 * o;
        float be = __ldg(&bias[oc_e]);
        float bo = __ldg(&bias[oc_e + 1]);
        float* ope = out + (((long)n * OC_ + oc_e)     * H_ + oh) * W_ + ow0;
        float* opo = out + (((long)n * OC_ + oc_e + 1) * H_ + oh) * W_ + ow0;
#pragma unroll
        for (int p = 0; p < TPX; p++) {
            ope[p] = lo2(acc2[o][p]) + be;
            opo[p] = hi2(acc2[o][p]) + bo;
        }
    }
}

// ---------------------------------------------------------------------------
// Launch: inputs (metadata order): x, q_weight, w_scale, w_min, bias
// ---------------------------------------------------------------------------
extern "C" void kernel_launch(void* const* d_in, const int* in_sizes, int n_in,
                              void* d_out, int out_size) {
    const float* x    = (const float*)d_in[0];
    const int*   q    = (const int*)  d_in[1];
    const float* ws   = (const float*)d_in[2];
    const float* wm   = (const float*)d_in[3];
    const float* bias = (const float*)d_in[4];
    float* out = (float*)d_out;

    (void)in_sizes; (void)n_in; (void)out_size;

    dequant_kernel<<<(OC_ * C_ * 9 + 255) / 256, 256>>>(q, ws, wm);

    dim3 grid(OC_ / OCT, H_, N_);   // (2, 56, 32)
    conv_kernel<<<grid, NTHR>>>(x, bias, out);
}